// round 7
// baseline (speedup 1.0000x reference)
#include <cuda_runtime.h>
#include <cuda_bf16.h>
#include <math.h>

#define T_STEPS 200
#define BATCH   128
#define DIN     784
#define HID     500
#define NOUT    10
#define MROWS   (BATCH * T_STEPS)   // 25600
#define DECAY_M 0.77880078307140487f
#define EPS_BN  1e-5f
#define NSTATB  800

typedef unsigned long long ull;

// ------------------------- device scratch (no allocs allowed) ---------------
__device__ float g_buf0[MROWS * DIN];
__device__ float g_buf1[MROWS * HID];
__device__ float g_buf2[MROWS * HID];
__device__ float g_buf3[MROWS * NOUT];
__device__ double g_psumd[NSTATB * DIN];
__device__ double g_psqd [NSTATB * DIN];
__device__ float g_mean[DIN];
__device__ float g_rs[DIN];

__device__ __forceinline__ float* bufsel(int s) {
    return s == 0 ? g_buf0 : (s == 1 ? g_buf1 : g_buf2);
}

// ------------------------- packed f32x2 helpers -----------------------------
__device__ __forceinline__ ull pack2(float lo, float hi) {
    ull r;
    asm("mov.b64 %0, {%1, %2};" : "=l"(r) : "f"(lo), "f"(hi));
    return r;
}
__device__ __forceinline__ void unpack2(ull v, float& lo, float& hi) {
    asm("mov.b64 {%0, %1}, %2;" : "=f"(lo), "=f"(hi) : "l"(v));
}

// Packed compensated accumulate — ALL ops in fma form so each maps to FFMA2.
// Per lane, value-identical to scalar kacc2:
//   y = rn(ab - c); t = rn(s + y); d = rn(t - s); cneg' = rn(y - d); s = t.
__device__ __forceinline__ void kaccf(ull a, ull b, ull& s, ull& cneg,
                                      ull ONE, ull NEGONE) {
    ull y, t, d;
    asm("fma.rn.f32x2 %0, %1, %2, %3;" : "=l"(y) : "l"(a), "l"(b), "l"(cneg));
    asm("fma.rn.f32x2 %0, %1, %2, %3;" : "=l"(t) : "l"(ONE), "l"(s), "l"(y));
    asm("fma.rn.f32x2 %0, %1, %2, %3;" : "=l"(d) : "l"(NEGONE), "l"(s), "l"(t));
    asm("fma.rn.f32x2 %0, %1, %2, %3;" : "=l"(cneg) : "l"(NEGONE), "l"(d), "l"(y));
    s = t;
}

// scalar version (gemm3)
__device__ __forceinline__ void kacc2(float a, float b, float& s, float& c) {
    float y = __fmaf_rn(a, b, -c);
    float t = __fadd_rn(s, y);
    c = __fsub_rn(__fsub_rn(t, s), y);
    s = t;
}

__device__ __forceinline__ float sigmoid_exact(float x) {
    return __fdiv_rn(1.0f, __fadd_rn(1.0f, expf(-x)));
}

// ======================= GEMM core (128x64 block, 8x4/thread) ===============
// MODE 0: A gathered from inputs[b,i,t];  MODE 1: A = bufsel row-major [M,K]
template <int MODE>
__device__ __forceinline__ void gemm_body(
    const float* __restrict__ Asrc, const float* __restrict__ B,
    const float* __restrict__ bias, float* __restrict__ Cdst, int N, int K) {
    __shared__ __align__(16) float As[8][132];
    __shared__ __align__(16) float Bs[8][68];
    int m0 = blockIdx.x * 128, n0 = blockIdx.y * 64;
    int tid = threadIdx.x;
    int tx = tid & 15, ty = tid >> 4;       // 16 cols x 16 rows
    const ull ONE = pack2(1.0f, 1.0f);
    const ull NEGONE = pack2(-1.0f, -1.0f);
    ull s2[8][2], c2[8][2];
#pragma unroll
    for (int i = 0; i < 8; i++)
#pragma unroll
        for (int j = 0; j < 2; j++) { s2[i][j] = 0ull; c2[i][j] = 0ull; }

    for (int k0 = 0; k0 < K; k0 += 8) {
#pragma unroll
        for (int l = 0; l < 4; l++) {
            int e = tid + l * 256;
            int m = e & 127, k = e >> 7;
            float v;
            if (MODE == 0) {
                int r = m0 + m;
                int bb = r / T_STEPS;
                int t  = r - bb * T_STEPS;
                v = Asrc[bb * (DIN * T_STEPS) + (k0 + k) * T_STEPS + t];
            } else {
                v = (k0 + k < K) ? Asrc[(m0 + m) * K + (k0 + k)] : 0.f;
            }
            As[k][m] = v;
        }
#pragma unroll
        for (int l = 0; l < 2; l++) {
            int e = tid + l * 256;
            int n = e >> 3, k = e & 7;
            float v = 0.f;
            if ((n0 + n < N) && (k0 + k < K)) v = B[(n0 + n) * K + (k0 + k)];
            Bs[k][n] = v;
        }
        __syncthreads();
#pragma unroll
        for (int k = 0; k < 8; k++) {
            float4 av0 = *reinterpret_cast<const float4*>(&As[k][ty * 8]);
            float4 av1 = *reinterpret_cast<const float4*>(&As[k][ty * 8 + 4]);
            const ull* pb = reinterpret_cast<const ull*>(&Bs[k][tx * 4]);
            ull b0 = pb[0], b1 = pb[1];
            ull a0 = pack2(av0.x, av0.x);
            ull a1 = pack2(av0.y, av0.y);
            ull a2 = pack2(av0.z, av0.z);
            ull a3 = pack2(av0.w, av0.w);
            ull a4 = pack2(av1.x, av1.x);
            ull a5 = pack2(av1.y, av1.y);
            ull a6 = pack2(av1.z, av1.z);
            ull a7 = pack2(av1.w, av1.w);
            kaccf(a0, b0, s2[0][0], c2[0][0], ONE, NEGONE);
            kaccf(a0, b1, s2[0][1], c2[0][1], ONE, NEGONE);
            kaccf(a1, b0, s2[1][0], c2[1][0], ONE, NEGONE);
            kaccf(a1, b1, s2[1][1], c2[1][1], ONE, NEGONE);
            kaccf(a2, b0, s2[2][0], c2[2][0], ONE, NEGONE);
            kaccf(a2, b1, s2[2][1], c2[2][1], ONE, NEGONE);
            kaccf(a3, b0, s2[3][0], c2[3][0], ONE, NEGONE);
            kaccf(a3, b1, s2[3][1], c2[3][1], ONE, NEGONE);
            kaccf(a4, b0, s2[4][0], c2[4][0], ONE, NEGONE);
            kaccf(a4, b1, s2[4][1], c2[4][1], ONE, NEGONE);
            kaccf(a5, b0, s2[5][0], c2[5][0], ONE, NEGONE);
            kaccf(a5, b1, s2[5][1], c2[5][1], ONE, NEGONE);
            kaccf(a6, b0, s2[6][0], c2[6][0], ONE, NEGONE);
            kaccf(a6, b1, s2[6][1], c2[6][1], ONE, NEGONE);
            kaccf(a7, b0, s2[7][0], c2[7][0], ONE, NEGONE);
            kaccf(a7, b1, s2[7][1], c2[7][1], ONE, NEGONE);
        }
        __syncthreads();
    }
#pragma unroll
    for (int i = 0; i < 8; i++) {
        int m = m0 + ty * 8 + i;
#pragma unroll
        for (int jj = 0; jj < 2; jj++) {
            float slo, shi, cnlo, cnhi;
            unpack2(s2[i][jj], slo, shi);
            unpack2(c2[i][jj], cnlo, cnhi);   // holds -c
            int n = n0 + tx * 4 + 2 * jj;
            if (n < N)
                Cdst[m * N + n] = __fadd_rn(__fadd_rn(slo, cnlo), bias[n]);
            if (n + 1 < N)
                Cdst[m * N + n + 1] = __fadd_rn(__fadd_rn(shi, cnhi), bias[n + 1]);
        }
    }
}

__global__ void __launch_bounds__(256) gemm_mlp_comp_kernel(
    const float* __restrict__ In, const float* __restrict__ W,
    const float* __restrict__ bias) {
    gemm_body<0>(In, W, bias, g_buf0, DIN, DIN);
}

__global__ void __launch_bounds__(256) gemm_nt_comp_kernel(
    int asel, int csel, const float* __restrict__ B,
    const float* __restrict__ bias, int N, int K) {
    gemm_body<1>(bufsel(asel), B, bias, bufsel(csel), N, K);
}

// ------------------------- BN stats: single pass fp64 sum + sumsq -----------
__global__ void bn_stats_kernel() {
    int blk = blockIdx.x;
    int tid = threadIdx.x;
    double ls[4] = {0.0, 0.0, 0.0, 0.0};
    double lq[4] = {0.0, 0.0, 0.0, 0.0};
    int r0 = blk * (MROWS / NSTATB);
    for (int r = r0; r < r0 + (MROWS / NSTATB); r++) {
        const float* row = g_buf0 + r * DIN;
#pragma unroll
        for (int j = 0; j < 4; j++) {
            int c = tid + j * 256;
            if (c < DIN) {
                double v = (double)row[c];
                ls[j] += v;
                lq[j] += v * v;
            }
        }
    }
#pragma unroll
    for (int j = 0; j < 4; j++) {
        int c = tid + j * 256;
        if (c < DIN) {
            g_psumd[blk * DIN + c] = ls[j];
            g_psqd [blk * DIN + c] = lq[j];
        }
    }
}

__global__ void bn_fin_kernel() {
    int c = blockIdx.x * blockDim.x + threadIdx.x;
    if (c >= DIN) return;
    double s = 0.0, q = 0.0;
    for (int i = 0; i < NSTATB; i++) {
        s += g_psumd[i * DIN + c];
        q += g_psqd [i * DIN + c];
    }
    float sumf = (float)s;
    g_mean[c] = __fdiv_rn(sumf, (float)MROWS);
    double meand = s / (double)MROWS;
    double vard = q / (double)MROWS - meand * meand;
    float var = (float)vard;
    g_rs[c] = rsqrtf(__fadd_rn(var, EPS_BN));
}

// ------------------------- fused BN apply + sigmoid + axon1 (in place) ------
__global__ void axon1_bn_kernel(const float* __restrict__ gamma,
                                const float* __restrict__ beta,
                                const float* __restrict__ a1,
                                const float* __restrict__ a2) {
    int idx = blockIdx.x * blockDim.x + threadIdx.x;
    if (idx >= BATCH * DIN) return;
    int b = idx / DIN, c = idx - b * DIN;
    float A1 = a1[c], A2 = a2[c];
    float mean = g_mean[c], rs = g_rs[c], gm = gamma[c], bt = beta[c];
    float p1 = 0.f, p2 = 0.f;
    int off = b * T_STEPS * DIN + c;
    for (int t = 0; t < T_STEPS; t++, off += DIN) {
        float v = __fsub_rn(g_buf0[off], mean);
        v = __fmul_rn(gm, v);
        v = __fmul_rn(v, rs);
        v = __fadd_rn(v, bt);
        float x = sigmoid_exact(v);
        float p = __fadd_rn(__fadd_rn(__fmul_rn(A1, p1), __fmul_rn(A2, p2)), x);
        g_buf0[off] = p;
        p2 = p1;
        p1 = p;
    }
}

// ------------------------- axon (layers 2,3): IIR over T (in place) ---------
__global__ void axon_kernel(int bsel, const float* __restrict__ a1,
                            const float* __restrict__ a2, int C) {
    float* buf = bufsel(bsel);
    int idx = blockIdx.x * blockDim.x + threadIdx.x;
    if (idx >= BATCH * C) return;
    int b = idx / C, c = idx - b * C;
    float A1 = a1[c], A2 = a2[c];
    float p1 = 0.f, p2 = 0.f;
    int off = b * T_STEPS * C + c;
    for (int t = 0; t < T_STEPS; t++, off += C) {
        float x = buf[off];
        float p = __fadd_rn(__fadd_rn(__fmul_rn(A1, p1), __fmul_rn(A2, p2)), x);
        buf[off] = p;
        p2 = p1;
        p1 = p;
    }
}

// ------------------------- LIF scan + dropout mask (mask read [B,H,T]) ------
__global__ void lif_kernel(int bsel, const float* __restrict__ mask) {
    float* buf = bufsel(bsel);
    int idx = blockIdx.x * blockDim.x + threadIdx.x;
    if (idx >= BATCH * HID) return;
    int b = idx / HID, c = idx - b * HID;
    float v = 0.f, s = 0.f;
    int off = b * T_STEPS * HID + c;
    int moff = (b * HID + c) * T_STEPS;
    for (int t = 0; t < T_STEPS; t++, off += HID) {
        float z = buf[off];
        v = __fadd_rn(__fmul_rn(__fmul_rn(DECAY_M, v), __fsub_rn(1.0f, s)), z);
        s = (v > 1.0f) ? 1.0f : 0.0f;
        buf[off] = __fmul_rn(s, mask[moff + t]);
    }
}

// ------------------------- GEMM3 (N=10): compensated ------------------------
__global__ void __launch_bounds__(256) gemm3_kernel(
    const float* __restrict__ W3, const float* __restrict__ b3) {
    __shared__ float sW[NOUT][HID];
    int tid = threadIdx.x;
    for (int i = tid; i < NOUT * HID; i += 256) sW[i / HID][i % HID] = W3[i];
    __syncthreads();
    int idx = blockIdx.x * 256 + tid;
    int r = idx / NOUT, o = idx - r * NOUT;
    const float* a = g_buf2 + r * HID;
    float s = 0.f, c = 0.f;
    for (int k = 0; k < HID; k++) kacc2(a[k], sW[o][k], s, c);
    float acc = __fsub_rn(s, c);
    g_buf3[r * NOUT + o] = __fadd_rn(acc, b3[o]);
}

// ------------------------- final LIF + output transpose [B,10,T] ------------
__global__ void lif3_out_kernel(float* __restrict__ out) {
    int idx = blockIdx.x * blockDim.x + threadIdx.x;
    if (idx >= BATCH * NOUT) return;
    int b = idx / NOUT, o = idx - b * NOUT;
    float v = 0.f, s = 0.f;
    for (int t = 0; t < T_STEPS; t++) {
        float z = g_buf3[(b * T_STEPS + t) * NOUT + o];
        v = __fadd_rn(__fmul_rn(__fmul_rn(DECAY_M, v), __fsub_rn(1.0f, s)), z);
        s = (v > 1.0f) ? 1.0f : 0.0f;
        out[(b * NOUT + o) * T_STEPS + t] = s;
    }
}

// ------------------------- launch -------------------------------------------
extern "C" void kernel_launch(void* const* d_in, const int* in_sizes, int n_in,
                              void* d_out, int out_size) {
    const float* inputs = (const float*)d_in[0];
    const float* W_mlp  = (const float*)d_in[1];
    const float* b_mlp  = (const float*)d_in[2];
    const float* gamma  = (const float*)d_in[3];
    const float* beta   = (const float*)d_in[4];
    const float* a1_1   = (const float*)d_in[5];
    const float* a2_1   = (const float*)d_in[6];
    const float* W1     = (const float*)d_in[7];
    const float* b1     = (const float*)d_in[8];
    const float* a1_2   = (const float*)d_in[9];
    const float* a2_2   = (const float*)d_in[10];
    const float* W2     = (const float*)d_in[11];
    const float* b2     = (const float*)d_in[12];
    const float* a1_3   = (const float*)d_in[13];
    const float* a2_3   = (const float*)d_in[14];
    const float* W3     = (const float*)d_in[15];
    const float* b3     = (const float*)d_in[16];
    const float* mask1  = (const float*)d_in[17];
    const float* mask2  = (const float*)d_in[18];
    float* out = (float*)d_out;

    gemm_mlp_comp_kernel<<<dim3(MROWS / 128, (DIN + 63) / 64), 256>>>(inputs, W_mlp, b_mlp);

    bn_stats_kernel<<<NSTATB, 256>>>();
    bn_fin_kernel<<<(DIN + 255) / 256, 256>>>();

    axon1_bn_kernel<<<(BATCH * DIN + 255) / 256, 256>>>(gamma, beta, a1_1, a2_1);
    gemm_nt_comp_kernel<<<dim3(MROWS / 128, (HID + 63) / 64), 256>>>(0, 1, W1, b1, HID, DIN);
    lif_kernel<<<(BATCH * HID + 255) / 256, 256>>>(1, mask1);

    axon_kernel<<<(BATCH * HID + 255) / 256, 256>>>(1, a1_2, a2_2, HID);
    gemm_nt_comp_kernel<<<dim3(MROWS / 128, (HID + 63) / 64), 256>>>(1, 2, W2, b2, HID, HID);
    lif_kernel<<<(BATCH * HID + 255) / 256, 256>>>(2, mask2);

    axon_kernel<<<(BATCH * HID + 255) / 256, 256>>>(2, a1_3, a2_3, HID);
    gemm3_kernel<<<MROWS * NOUT / 256, 256>>>(W3, b3);
    lif3_out_kernel<<<(BATCH * NOUT + 255) / 256, 256>>>(out);
}

// round 8
// speedup vs baseline: 1.1013x; 1.1013x over previous
#include <cuda_runtime.h>
#include <cuda_bf16.h>
#include <math.h>

#define T_STEPS 200
#define BATCH   128
#define DIN     784
#define HID     500
#define NOUT    10
#define MROWS   (BATCH * T_STEPS)   // 25600
#define DECAY_M 0.77880078307140487f
#define EPS_BN  1e-5f
#define NSTATB  800

typedef unsigned long long ull;

// ------------------------- device scratch (no allocs allowed) ---------------
__device__ float g_buf0[MROWS * DIN];
__device__ float g_buf1[MROWS * HID];
__device__ float g_buf2[MROWS * HID];
__device__ float g_buf3[MROWS * NOUT];
__device__ double g_psumd[NSTATB * DIN];
__device__ double g_psqd [NSTATB * DIN];
__device__ float g_mean[DIN];
__device__ float g_rs[DIN];
// Opaque packed constants: mutable __device__ data => ptxas cannot fold the
// fma-with-(+/-1) back into adds; all four kacc ops stay FFMA2.
__device__ ull g_onepair    = 0x3F8000003F800000ULL;   // {1.0f, 1.0f}
__device__ ull g_negonepair = 0xBF800000BF800000ULL;   // {-1.0f, -1.0f}

__device__ __forceinline__ float* bufsel(int s) {
    return s == 0 ? g_buf0 : (s == 1 ? g_buf1 : g_buf2);
}

// ------------------------- packed f32x2 helpers -----------------------------
__device__ __forceinline__ ull pack2(float lo, float hi) {
    ull r;
    asm("mov.b64 %0, {%1, %2};" : "=l"(r) : "f"(lo), "f"(hi));
    return r;
}
__device__ __forceinline__ void unpack2(ull v, float& lo, float& hi) {
    asm("mov.b64 {%0, %1}, %2;" : "=f"(lo), "=f"(hi) : "l"(v));
}

// Packed compensated accumulate — all four ops are 3-register fma.rn.f32x2.
// Per lane, value-identical to scalar kacc2:
//   y = rn(ab - c); t = rn(s + y); d = rn(t - s); cneg' = rn(y - d); s = t.
__device__ __forceinline__ void kaccf(ull a, ull b, ull& s, ull& cneg,
                                      ull ONE, ull NEGONE) {
    ull y, t, d;
    asm("fma.rn.f32x2 %0, %1, %2, %3;" : "=l"(y) : "l"(a), "l"(b), "l"(cneg));
    asm("fma.rn.f32x2 %0, %1, %2, %3;" : "=l"(t) : "l"(ONE), "l"(s), "l"(y));
    asm("fma.rn.f32x2 %0, %1, %2, %3;" : "=l"(d) : "l"(NEGONE), "l"(s), "l"(t));
    asm("fma.rn.f32x2 %0, %1, %2, %3;" : "=l"(cneg) : "l"(NEGONE), "l"(d), "l"(y));
    s = t;
}

// scalar version (gemm3)
__device__ __forceinline__ void kacc2(float a, float b, float& s, float& c) {
    float y = __fmaf_rn(a, b, -c);
    float t = __fadd_rn(s, y);
    c = __fsub_rn(__fsub_rn(t, s), y);
    s = t;
}

__device__ __forceinline__ float sigmoid_exact(float x) {
    return __fdiv_rn(1.0f, __fadd_rn(1.0f, expf(-x)));
}

// ======================= GEMM core (64x64 block, 4x4/thread packed) =========
// MODE 0: A gathered from inputs[b,i,t];  MODE 1: A row-major [M,K]
template <int MODE>
__device__ __forceinline__ void gemm_body(
    const float* __restrict__ Asrc, const float* __restrict__ B,
    const float* __restrict__ bias, float* __restrict__ Cdst, int N, int K) {
    __shared__ __align__(16) float As[8][68];
    __shared__ __align__(16) float Bs[8][68];
    int m0 = blockIdx.x * 64, n0 = blockIdx.y * 64;
    int tid = threadIdx.x;
    int tx = tid & 15, ty = tid >> 4;
    const ull ONE = g_onepair;        // opaque loads (once per thread)
    const ull NEGONE = g_negonepair;
    ull s2[4][2], c2[4][2];
#pragma unroll
    for (int i = 0; i < 4; i++)
#pragma unroll
        for (int j = 0; j < 2; j++) { s2[i][j] = 0ull; c2[i][j] = 0ull; }

    for (int k0 = 0; k0 < K; k0 += 8) {
#pragma unroll
        for (int l = 0; l < 2; l++) {
            int e = tid + l * 256;
            int m = e & 63, k = e >> 6;
            float v;
            if (MODE == 0) {
                int r = m0 + m;
                int bb = r / T_STEPS;
                int t  = r - bb * T_STEPS;
                v = Asrc[bb * (DIN * T_STEPS) + (k0 + k) * T_STEPS + t];
            } else {
                v = (k0 + k < K) ? Asrc[(m0 + m) * K + (k0 + k)] : 0.f;
            }
            As[k][m] = v;
        }
#pragma unroll
        for (int l = 0; l < 2; l++) {
            int e = tid + l * 256;
            int n = e >> 3, k = e & 7;
            float v = 0.f;
            if ((n0 + n < N) && (k0 + k < K)) v = B[(n0 + n) * K + (k0 + k)];
            Bs[k][n] = v;
        }
        __syncthreads();
#pragma unroll
        for (int k = 0; k < 8; k++) {
            float4 av = *reinterpret_cast<const float4*>(&As[k][ty * 4]);
            const ull* pb = reinterpret_cast<const ull*>(&Bs[k][tx * 4]);
            ull b0 = pb[0], b1 = pb[1];
            ull a0 = pack2(av.x, av.x);
            ull a1 = pack2(av.y, av.y);
            ull a2 = pack2(av.z, av.z);
            ull a3 = pack2(av.w, av.w);
            kaccf(a0, b0, s2[0][0], c2[0][0], ONE, NEGONE);
            kaccf(a0, b1, s2[0][1], c2[0][1], ONE, NEGONE);
            kaccf(a1, b0, s2[1][0], c2[1][0], ONE, NEGONE);
            kaccf(a1, b1, s2[1][1], c2[1][1], ONE, NEGONE);
            kaccf(a2, b0, s2[2][0], c2[2][0], ONE, NEGONE);
            kaccf(a2, b1, s2[2][1], c2[2][1], ONE, NEGONE);
            kaccf(a3, b0, s2[3][0], c2[3][0], ONE, NEGONE);
            kaccf(a3, b1, s2[3][1], c2[3][1], ONE, NEGONE);
        }
        __syncthreads();
    }
#pragma unroll
    for (int i = 0; i < 4; i++) {
        int m = m0 + ty * 4 + i;
#pragma unroll
        for (int jj = 0; jj < 2; jj++) {
            float slo, shi, cnlo, cnhi;
            unpack2(s2[i][jj], slo, shi);
            unpack2(c2[i][jj], cnlo, cnhi);   // holds -c
            int n = n0 + tx * 4 + 2 * jj;
            if (n < N)
                Cdst[m * N + n] = __fadd_rn(__fadd_rn(slo, cnlo), bias[n]);
            if (n + 1 < N)
                Cdst[m * N + n + 1] = __fadd_rn(__fadd_rn(shi, cnhi), bias[n + 1]);
        }
    }
}

__global__ void __launch_bounds__(256) gemm_mlp_comp_kernel(
    const float* __restrict__ In, const float* __restrict__ W,
    const float* __restrict__ bias) {
    gemm_body<0>(In, W, bias, g_buf0, DIN, DIN);
}

__global__ void __launch_bounds__(256) gemm_nt_comp_kernel(
    int asel, int csel, const float* __restrict__ B,
    const float* __restrict__ bias, int N, int K) {
    gemm_body<1>(bufsel(asel), B, bias, bufsel(csel), N, K);
}

// ------------------------- BN stats: single pass fp64 sum + sumsq -----------
__global__ void bn_stats_kernel() {
    int blk = blockIdx.x;
    int tid = threadIdx.x;
    double ls[4] = {0.0, 0.0, 0.0, 0.0};
    double lq[4] = {0.0, 0.0, 0.0, 0.0};
    int r0 = blk * (MROWS / NSTATB);
    for (int r = r0; r < r0 + (MROWS / NSTATB); r++) {
        const float* row = g_buf0 + r * DIN;
#pragma unroll
        for (int j = 0; j < 4; j++) {
            int c = tid + j * 256;
            if (c < DIN) {
                double v = (double)row[c];
                ls[j] += v;
                lq[j] += v * v;
            }
        }
    }
#pragma unroll
    for (int j = 0; j < 4; j++) {
        int c = tid + j * 256;
        if (c < DIN) {
            g_psumd[blk * DIN + c] = ls[j];
            g_psqd [blk * DIN + c] = lq[j];
        }
    }
}

__global__ void bn_fin_kernel() {
    int c = blockIdx.x * blockDim.x + threadIdx.x;
    if (c >= DIN) return;
    double s = 0.0, q = 0.0;
    for (int i = 0; i < NSTATB; i++) {
        s += g_psumd[i * DIN + c];
        q += g_psqd [i * DIN + c];
    }
    float sumf = (float)s;
    g_mean[c] = __fdiv_rn(sumf, (float)MROWS);
    double meand = s / (double)MROWS;
    double vard = q / (double)MROWS - meand * meand;
    float var = (float)vard;
    g_rs[c] = rsqrtf(__fadd_rn(var, EPS_BN));
}

// ------------------------- fused BN apply + sigmoid + axon1 (in place) ------
__global__ void axon1_bn_kernel(const float* __restrict__ gamma,
                                const float* __restrict__ beta,
                                const float* __restrict__ a1,
                                const float* __restrict__ a2) {
    int idx = blockIdx.x * blockDim.x + threadIdx.x;
    if (idx >= BATCH * DIN) return;
    int b = idx / DIN, c = idx - b * DIN;
    float A1 = a1[c], A2 = a2[c];
    float mean = g_mean[c], rs = g_rs[c], gm = gamma[c], bt = beta[c];
    float p1 = 0.f, p2 = 0.f;
    int off = b * T_STEPS * DIN + c;
    for (int t = 0; t < T_STEPS; t++, off += DIN) {
        float v = __fsub_rn(g_buf0[off], mean);
        v = __fmul_rn(gm, v);
        v = __fmul_rn(v, rs);
        v = __fadd_rn(v, bt);
        float x = sigmoid_exact(v);
        float p = __fadd_rn(__fadd_rn(__fmul_rn(A1, p1), __fmul_rn(A2, p2)), x);
        g_buf0[off] = p;
        p2 = p1;
        p1 = p;
    }
}

// ------------------------- axon (layers 2,3): IIR over T (in place) ---------
__global__ void axon_kernel(int bsel, const float* __restrict__ a1,
                            const float* __restrict__ a2, int C) {
    float* buf = bufsel(bsel);
    int idx = blockIdx.x * blockDim.x + threadIdx.x;
    if (idx >= BATCH * C) return;
    int b = idx / C, c = idx - b * C;
    float A1 = a1[c], A2 = a2[c];
    float p1 = 0.f, p2 = 0.f;
    int off = b * T_STEPS * C + c;
    for (int t = 0; t < T_STEPS; t++, off += C) {
        float x = buf[off];
        float p = __fadd_rn(__fadd_rn(__fmul_rn(A1, p1), __fmul_rn(A2, p2)), x);
        buf[off] = p;
        p2 = p1;
        p1 = p;
    }
}

// ------------------------- LIF scan + dropout mask (mask read [B,H,T]) ------
__global__ void lif_kernel(int bsel, const float* __restrict__ mask) {
    float* buf = bufsel(bsel);
    int idx = blockIdx.x * blockDim.x + threadIdx.x;
    if (idx >= BATCH * HID) return;
    int b = idx / HID, c = idx - b * HID;
    float v = 0.f, s = 0.f;
    int off = b * T_STEPS * HID + c;
    int moff = (b * HID + c) * T_STEPS;
    for (int t = 0; t < T_STEPS; t++, off += HID) {
        float z = buf[off];
        v = __fadd_rn(__fmul_rn(__fmul_rn(DECAY_M, v), __fsub_rn(1.0f, s)), z);
        s = (v > 1.0f) ? 1.0f : 0.0f;
        buf[off] = __fmul_rn(s, mask[moff + t]);
    }
}

// ------------------------- GEMM3 (N=10): compensated ------------------------
__global__ void __launch_bounds__(256) gemm3_kernel(
    const float* __restrict__ W3, const float* __restrict__ b3) {
    __shared__ float sW[NOUT][HID];
    int tid = threadIdx.x;
    for (int i = tid; i < NOUT * HID; i += 256) sW[i / HID][i % HID] = W3[i];
    __syncthreads();
    int idx = blockIdx.x * 256 + tid;
    int r = idx / NOUT, o = idx - r * NOUT;
    const float* a = g_buf2 + r * HID;
    float s = 0.f, c = 0.f;
    for (int k = 0; k < HID; k++) kacc2(a[k], sW[o][k], s, c);
    float acc = __fsub_rn(s, c);
    g_buf3[r * NOUT + o] = __fadd_rn(acc, b3[o]);
}

// ------------------------- final LIF + output transpose [B,10,T] ------------
__global__ void lif3_out_kernel(float* __restrict__ out) {
    int idx = blockIdx.x * blockDim.x + threadIdx.x;
    if (idx >= BATCH * NOUT) return;
    int b = idx / NOUT, o = idx - b * NOUT;
    float v = 0.f, s = 0.f;
    for (int t = 0; t < T_STEPS; t++) {
        float z = g_buf3[(b * T_STEPS + t) * NOUT + o];
        v = __fadd_rn(__fmul_rn(__fmul_rn(DECAY_M, v), __fsub_rn(1.0f, s)), z);
        s = (v > 1.0f) ? 1.0f : 0.0f;
        out[(b * NOUT + o) * T_STEPS + t] = s;
    }
}

// ------------------------- launch -------------------------------------------
extern "C" void kernel_launch(void* const* d_in, const int* in_sizes, int n_in,
                              void* d_out, int out_size) {
    const float* inputs = (const float*)d_in[0];
    const float* W_mlp  = (const float*)d_in[1];
    const float* b_mlp  = (const float*)d_in[2];
    const float* gamma  = (const float*)d_in[3];
    const float* beta   = (const float*)d_in[4];
    const float* a1_1   = (const float*)d_in[5];
    const float* a2_1   = (const float*)d_in[6];
    const float* W1     = (const float*)d_in[7];
    const float* b1     = (const float*)d_in[8];
    const float* a1_2   = (const float*)d_in[9];
    const float* a2_2   = (const float*)d_in[10];
    const float* W2     = (const float*)d_in[11];
    const float* b2     = (const float*)d_in[12];
    const float* a1_3   = (const float*)d_in[13];
    const float* a2_3   = (const float*)d_in[14];
    const float* W3     = (const float*)d_in[15];
    const float* b3     = (const float*)d_in[16];
    const float* mask1  = (const float*)d_in[17];
    const float* mask2  = (const float*)d_in[18];
    float* out = (float*)d_out;

    gemm_mlp_comp_kernel<<<dim3(MROWS / 64, (DIN + 63) / 64), 256>>>(inputs, W_mlp, b_mlp);

    bn_stats_kernel<<<NSTATB, 256>>>();
    bn_fin_kernel<<<(DIN + 255) / 256, 256>>>();

    axon1_bn_kernel<<<(BATCH * DIN + 255) / 256, 256>>>(gamma, beta, a1_1, a2_1);
    gemm_nt_comp_kernel<<<dim3(MROWS / 64, (HID + 63) / 64), 256>>>(0, 1, W1, b1, HID, DIN);
    lif_kernel<<<(BATCH * HID + 255) / 256, 256>>>(1, mask1);

    axon_kernel<<<(BATCH * HID + 255) / 256, 256>>>(1, a1_2, a2_2, HID);
    gemm_nt_comp_kernel<<<dim3(MROWS / 64, (HID + 63) / 64), 256>>>(1, 2, W2, b2, HID, HID);
    lif_kernel<<<(BATCH * HID + 255) / 256, 256>>>(2, mask2);

    axon_kernel<<<(BATCH * HID + 255) / 256, 256>>>(2, a1_3, a2_3, HID);
    gemm3_kernel<<<MROWS * NOUT / 256, 256>>>(W3, b3);
    lif3_out_kernel<<<(BATCH * NOUT + 255) / 256, 256>>>(out);
}